// round 3
// baseline (speedup 1.0000x reference)
#include <cuda_runtime.h>
#include <math.h>

#define NB 32
#define NC 64
#define NH 128
#define NW 128
#define QD 8
#define HWSZ (NH*NW)
#define NEGV (-1e4f)

// ---- device scratch ----
__device__ float g_Q[(size_t)NB*QD*HWSZ];     // [b][q][h][w]
__device__ float g_K[(size_t)NB*QD*HWSZ];     // [b][q][h][w]
__device__ float g_V[(size_t)NB*NC*HWSZ];     // [b][c][h][w]
__device__ float g_MH[(size_t)NB*NC*QD*NW];   // [b][c*8+q][w]  (h-half 0)
__device__ float g_MH2[(size_t)NB*NC*QD*NW];  // [b][c*8+q][w]  (h-half 1)
__device__ float g_MW[(size_t)NB*NH*NC*QD];   // [b][h][c*8+q]

// ---- packed f32x2 helpers (FFMA2 path, sm_10x) ----
__device__ __forceinline__ unsigned long long pack2(float a, float b) {
    unsigned long long r;
    asm("mov.b64 %0, {%1, %2};" : "=l"(r) : "f"(a), "f"(b));
    return r;
}
__device__ __forceinline__ void unpack2(unsigned long long v, float& a, float& b) {
    asm("mov.b64 {%0, %1}, %2;" : "=f"(a), "=f"(b) : "l"(v));
}
__device__ __forceinline__ void ffma2(unsigned long long& d,
                                      unsigned long long a, unsigned long long b) {
    asm("fma.rn.f32x2 %0, %1, %2, %0;" : "+l"(d) : "l"(a), "l"(b));
}

// ---------------------------------------------------------------
// Kernel A: fused 1x1 projections with packed f32x2 accumulation.
// NO min-CTA clamp: accumulators must live in registers (96+ regs).
// ---------------------------------------------------------------
__global__ void __launch_bounds__(256) kproj(
    const float* __restrict__ x,
    const float* __restrict__ wq, const float* __restrict__ bq,
    const float* __restrict__ wk, const float* __restrict__ bk,
    const float* __restrict__ wv, const float* __restrict__ bv)
{
    __shared__ __align__(16) float swq[NC*QD];   // [c][o]
    __shared__ __align__(16) float swk[NC*QD];   // [c][o]
    __shared__ __align__(16) float swv[NC*NC];   // [c][o]
    int tid = threadIdx.x;
    for (int i = tid; i < NC*QD; i += 256) {
        int o = i / NC, c = i % NC;
        swq[c*QD + o] = wq[i];
        swk[c*QD + o] = wk[i];
    }
    for (int i = tid; i < NC*NC; i += 256) {
        int o = i / NC, c = i % NC;
        swv[c*NC + o] = wv[i];
    }
    __syncthreads();

    int gid = blockIdx.x * 256 + tid;
    int b = gid / HWSZ, p = gid % HWSZ;
    const float* xb = x + (size_t)b*NC*HWSZ + p;

    unsigned long long aq[QD/2], ak[QD/2], av[NC/2];
#pragma unroll
    for (int j = 0; j < QD/2; j++) {
        aq[j] = pack2(bq[2*j], bq[2*j+1]);
        ak[j] = pack2(bk[2*j], bk[2*j+1]);
    }
#pragma unroll
    for (int j = 0; j < NC/2; j++) av[j] = pack2(bv[2*j], bv[2*j+1]);

#pragma unroll 2
    for (int c = 0; c < NC; c++) {
        float xv = xb[(size_t)c*HWSZ];
        unsigned long long xv2 = pack2(xv, xv);
        const ulonglong2* wv2 = reinterpret_cast<const ulonglong2*>(&swv[c*NC]);
#pragma unroll
        for (int j = 0; j < NC/4; j++) {
            ulonglong2 wp = wv2[j];
            ffma2(av[2*j+0], xv2, wp.x);
            ffma2(av[2*j+1], xv2, wp.y);
        }
        const ulonglong2* wq2 = reinterpret_cast<const ulonglong2*>(&swq[c*QD]);
        const ulonglong2* wk2 = reinterpret_cast<const ulonglong2*>(&swk[c*QD]);
#pragma unroll
        for (int j = 0; j < QD/4; j++) {
            ulonglong2 a = wq2[j], kk = wk2[j];
            ffma2(aq[2*j+0], xv2, a.x);
            ffma2(aq[2*j+1], xv2, a.y);
            ffma2(ak[2*j+0], xv2, kk.x);
            ffma2(ak[2*j+1], xv2, kk.y);
        }
    }

    float* Qb = g_Q + (size_t)b*QD*HWSZ + p;
    float* Kb = g_K + (size_t)b*QD*HWSZ + p;
    float* Vb = g_V + (size_t)b*NC*HWSZ + p;
#pragma unroll
    for (int j = 0; j < QD/2; j++) {
        float v0, v1;
        unpack2(aq[j], v0, v1);
        Qb[(size_t)(2*j+0)*HWSZ] = fmaxf(v0, 0.f) + log1pf(expf(-fabsf(v0)));
        Qb[(size_t)(2*j+1)*HWSZ] = fmaxf(v1, 0.f) + log1pf(expf(-fabsf(v1)));
        unpack2(ak[j], v0, v1);
        Kb[(size_t)(2*j+0)*HWSZ] = fmaxf(v0, 0.f) + log1pf(expf(-fabsf(v0)));
        Kb[(size_t)(2*j+1)*HWSZ] = fmaxf(v1, 0.f) + log1pf(expf(-fabsf(v1)));
    }
#pragma unroll
    for (int j = 0; j < NC/2; j++) {
        float v0, v1;
        unpack2(av[j], v0, v1);
        Vb[(size_t)(2*j+0)*HWSZ] = v0;
        Vb[(size_t)(2*j+1)*HWSZ] = v1;
    }
}

// ---------------------------------------------------------------
// Kernel B: M_W[b,h,c,q] = sum_w V[b,c,h,w] * K[b,q,h,w]
// ---------------------------------------------------------------
__global__ void __launch_bounds__(256) kmw()
{
    __shared__ float sV[NC*129];
    __shared__ float sK[QD*129];
    int tid = threadIdx.x;
    int b = blockIdx.x / NH, h = blockIdx.x % NH;
    const float* Vrow = g_V + (size_t)b*NC*HWSZ + h*NW;
    const float* Krow = g_K + (size_t)b*QD*HWSZ + h*NW;

#pragma unroll
    for (int i = 0; i < 8; i++) {
        int idx4 = tid + i*256;
        int c = idx4 >> 5, r = idx4 & 31;
        float4 v = *reinterpret_cast<const float4*>(Vrow + (size_t)c*HWSZ + r*4);
        sV[c*129 + r*4 + 0] = v.x; sV[c*129 + r*4 + 1] = v.y;
        sV[c*129 + r*4 + 2] = v.z; sV[c*129 + r*4 + 3] = v.w;
    }
    {
        int q = tid >> 5, r = tid & 31;
        float4 v = *reinterpret_cast<const float4*>(Krow + (size_t)q*HWSZ + r*4);
        sK[q*129 + r*4 + 0] = v.x; sK[q*129 + r*4 + 1] = v.y;
        sK[q*129 + r*4 + 2] = v.z; sK[q*129 + r*4 + 3] = v.w;
    }
    __syncthreads();

    int c = tid >> 2;
    int q0 = (tid & 3) * 2;
    float a0 = 0.f, a1 = 0.f;
#pragma unroll 4
    for (int w = 0; w < NW; w++) {
        float v = sV[c*129 + w];
        a0 = fmaf(v, sK[q0*129 + w],     a0);
        a1 = fmaf(v, sK[(q0+1)*129 + w], a1);
    }
    float2* out = reinterpret_cast<float2*>(g_MW + ((size_t)b*NH + h)*NC*QD);
    out[tid] = make_float2(a0, a1);
}

// ---------------------------------------------------------------
// Kernel C: partial M_H over an h-half.
// grid = NB * 4 wtiles * 2 h-halves; one block = (b, w-tile32, half).
// ---------------------------------------------------------------
__global__ void __launch_bounds__(1024) kmh()
{
    __shared__ float sV[NC*4*32];
    __shared__ float sK[QD*4*32];
    int tid = threadIdx.x;
    int blk = blockIdx.x;
    int half = blk & 1;
    int w0 = ((blk >> 1) & 3) * 32;
    int b = blk >> 3;
    int w = tid & 31, ch = tid >> 5;

    float acc[16];
#pragma unroll
    for (int i = 0; i < 16; i++) acc[i] = 0.f;

    const float* Vb = g_V + (size_t)b*NC*HWSZ + w0;
    const float* Kb = g_K + (size_t)b*QD*HWSZ + w0;
    int hbeg = half * (NH/2), hend = hbeg + NH/2;

    for (int h0 = hbeg; h0 < hend; h0 += 4) {
        __syncthreads();
#pragma unroll
        for (int i = 0; i < 2; i++) {
            int idx4 = tid + i*1024;
            int c = idx4 >> 5, rem = idx4 & 31;
            int hh = rem >> 3, j = rem & 7;
            float4 v = *reinterpret_cast<const float4*>(
                Vb + (size_t)c*HWSZ + (h0 + hh)*NW + j*4);
            *reinterpret_cast<float4*>(&sV[(c*4 + hh)*32 + j*4]) = v;
        }
        if (tid < 256) {
            int q = tid >> 5, rem = tid & 31;
            int hh = rem >> 3, j = rem & 7;
            float4 v = *reinterpret_cast<const float4*>(
                Kb + (size_t)q*HWSZ + (h0 + hh)*NW + j*4);
            *reinterpret_cast<float4*>(&sK[(q*4 + hh)*32 + j*4]) = v;
        }
        __syncthreads();
#pragma unroll
        for (int hh = 0; hh < 4; hh++) {
            float v0 = sV[(ch*4 + hh)*32 + w];
            float v1 = sV[((ch + 32)*4 + hh)*32 + w];
#pragma unroll
            for (int q = 0; q < QD; q++) {
                float kk = sK[(q*4 + hh)*32 + w];
                acc[q]     = fmaf(v0, kk, acc[q]);
                acc[8 + q] = fmaf(v1, kk, acc[8 + q]);
            }
        }
    }
    float* out = (half ? g_MH2 : g_MH) + (size_t)b*NC*QD*NW + w0 + w;
#pragma unroll
    for (int q = 0; q < QD; q++) {
        out[(size_t)(ch*QD + q)*NW]        = acc[q];
        out[(size_t)((ch + 32)*QD + q)*NW] = acc[8 + q];
    }
}

// ---------------------------------------------------------------
// Kernel D: out = gamma*( sum_q Q*(MH+MW) + NEG*V ) + x
// Block = (b, c-half of 32, 8h x 32w). 40KB static smem -> 5 CTAs/SM.
// MH = MH_half0 + MH_half1 summed during the smem fill.
// ---------------------------------------------------------------
__global__ void __launch_bounds__(256, 5) kout(
    const float* __restrict__ x,
    const float* __restrict__ gamma,
    float* __restrict__ out)
{
    __shared__ __align__(16) float sMH[32*QD*32];   // [c_loc*8+q][w32]  32KB
    __shared__ __align__(16) float sMW[8*32*QD];    // [hl][c_loc*8+q]    8KB
    int tid = threadIdx.x;
    int w0 = blockIdx.x * 32, h0 = blockIdx.y * 8;
    int b  = blockIdx.z >> 1;
    int c0 = (blockIdx.z & 1) * 32;
    int lane = tid & 31, hl = tid >> 5;

#pragma unroll
    for (int i = 0; i < 8; i++) {
        int idx4 = tid + i*256;
        int cql = idx4 >> 3, j = idx4 & 7;
        size_t off = ((size_t)b*NC*QD + c0*QD + cql)*NW + w0 + j*4;
        float4 v  = *reinterpret_cast<const float4*>(g_MH  + off);
        float4 v2 = *reinterpret_cast<const float4*>(g_MH2 + off);
        v.x += v2.x; v.y += v2.y; v.z += v2.z; v.w += v2.w;
        *reinterpret_cast<float4*>(&sMH[cql*32 + j*4]) = v;
    }
#pragma unroll
    for (int i = 0; i < 2; i++) {
        int idx4 = tid + i*256;
        int hh = idx4 >> 6, j = idx4 & 63;
        float4 v = *reinterpret_cast<const float4*>(
            g_MW + ((size_t)(b*NH + h0 + hh)*NC + c0)*QD + j*4);
        *reinterpret_cast<float4*>(&sMW[hh*(32*QD) + j*4]) = v;
    }

    int h = h0 + hl, w = w0 + lane;
    float Qr[QD];
#pragma unroll
    for (int q = 0; q < QD; q++)
        Qr[q] = g_Q[((size_t)b*QD + q)*HWSZ + h*NW + w];
    float gm = gamma[0];
    __syncthreads();

    const float* Vp = g_V + ((size_t)b*NC + c0)*HWSZ + h*NW + w;
    const float* Xp = x   + ((size_t)b*NC + c0)*HWSZ + h*NW + w;
    float*       Op = out + ((size_t)b*NC + c0)*HWSZ + h*NW + w;

#pragma unroll
    for (int cc = 0; cc < 32; cc += 4) {
        float v[4], xr[4];
#pragma unroll
        for (int u = 0; u < 4; u++) {
            v[u]  = Vp[(size_t)(cc+u)*HWSZ];
            xr[u] = Xp[(size_t)(cc+u)*HWSZ];
        }
#pragma unroll
        for (int u = 0; u < 4; u++) {
            int c = cc + u;
            const float* mh = &sMH[c*QD*32 + lane];
            const float4* mwp = reinterpret_cast<const float4*>(&sMW[hl*(32*QD) + c*QD]);
            float4 a = mwp[0], bb = mwp[1];
            float acc;
            acc  = (mh[0]   + a.x)  * Qr[0];
            acc += (mh[32]  + a.y)  * Qr[1];
            acc += (mh[64]  + a.z)  * Qr[2];
            acc += (mh[96]  + a.w)  * Qr[3];
            acc += (mh[128] + bb.x) * Qr[4];
            acc += (mh[160] + bb.y) * Qr[5];
            acc += (mh[192] + bb.z) * Qr[6];
            acc += (mh[224] + bb.w) * Qr[7];
            Op[(size_t)c*HWSZ] = fmaf(gm, fmaf(NEGV, v[u], acc), xr[u]);
        }
    }
}

// ---------------------------------------------------------------
extern "C" void kernel_launch(void* const* d_in, const int* in_sizes, int n_in,
                              void* d_out, int out_size)
{
    const float* x     = (const float*)d_in[0];
    const float* wq    = (const float*)d_in[1];
    const float* bq    = (const float*)d_in[2];
    const float* wk    = (const float*)d_in[3];
    const float* bk    = (const float*)d_in[4];
    const float* wv    = (const float*)d_in[5];
    const float* bv    = (const float*)d_in[6];
    const float* gamma = (const float*)d_in[7];
    float* out = (float*)d_out;

    kproj<<<(NB*HWSZ)/256, 256>>>(x, wq, bq, wk, bk, wv, bv);
    kmw<<<NB*NH, 256>>>();
    kmh<<<NB*8, 1024>>>();
    kout<<<dim3(NW/32, NH/8, NB*2), 256>>>(x, gamma, out);
}

// round 4
// speedup vs baseline: 1.0347x; 1.0347x over previous
#include <cuda_runtime.h>
#include <math.h>

#define NB 32
#define NC 64
#define NH 128
#define NW 128
#define QD 8
#define HWSZ (NH*NW)
#define NEGV (-1e4f)
#define NOUT 80          // 64 V + 8 Q + 8 K
#define PTILE 256        // pixels per kproj block

// ---- device scratch ----
__device__ float g_Q[(size_t)NB*QD*HWSZ];     // [b][q][h][w]
__device__ float g_K[(size_t)NB*QD*HWSZ];     // [b][q][h][w]
__device__ float g_V[(size_t)NB*NC*HWSZ];     // [b][c][h][w]
__device__ float g_MH[(size_t)NB*NC*QD*NW];   // [b][c*8+q][w]
__device__ float g_MW[(size_t)NB*NH*NC*QD];   // [b][h][c*8+q]

// ---- packed f32x2 helpers ----
__device__ __forceinline__ unsigned long long pack2(float a, float b) {
    unsigned long long r;
    asm("mov.b64 %0, {%1, %2};" : "=l"(r) : "f"(a), "f"(b));
    return r;
}
__device__ __forceinline__ void unpack2(unsigned long long v, float& a, float& b) {
    asm("mov.b64 {%0, %1}, %2;" : "=f"(a), "=f"(b) : "l"(v));
}
__device__ __forceinline__ void ffma2(unsigned long long& d,
                                      unsigned long long a, unsigned long long b) {
    asm("fma.rn.f32x2 %0, %1, %2, %0;" : "+l"(d) : "l"(a), "l"(b));
}
__device__ __forceinline__ float softplusf(float v) {
    return fmaxf(v, 0.f) + log1pf(expf(-fabsf(v)));
}

// ---------------------------------------------------------------
// Kernel A: 1x1 projections as a register-tiled GEMM.
// Block = 256-pixel tile, 160 threads (5 warps x 16 output rows).
// Thread tile = 8 output-PAIRS (f32x2 lanes) x 8 pixels = 64 u64 accs.
// Per k-step/warp: 8 bcast LDS.64 (w-pairs) + 8 distinct LDS.32 (x).
// ---------------------------------------------------------------
__global__ void __launch_bounds__(160) kproj(
    const float* __restrict__ x,
    const float* __restrict__ wq, const float* __restrict__ bq,
    const float* __restrict__ wk, const float* __restrict__ bk,
    const float* __restrict__ wv, const float* __restrict__ bv)
{
    extern __shared__ float sm[];
    float* sX = sm;                       // [c][256]   16384 floats
    float* sW = sm + NC*PTILE;            // [c][80]     5120 floats
    float* sB = sW + NC*NOUT;             // [80]

    int tid = threadIdx.x;
    int b  = blockIdx.x >> 6;
    int p0 = (blockIdx.x & 63) * PTILE;

    // stage weights transposed: sW[c*80+o] = W[o][c]  (L2-hot after block 0)
    for (int i = tid; i < NC*NOUT; i += 160) {
        int c = i / NOUT, o = i % NOUT;
        float v;
        if (o < 64)      v = wv[o*NC + c];
        else if (o < 72) v = wq[(o-64)*NC + c];
        else             v = wk[(o-72)*NC + c];
        sW[i] = v;
    }
    if (tid < NOUT) {
        int o = tid;
        sB[o] = (o < 64) ? bv[o] : (o < 72 ? bq[o-64] : bk[o-72]);
    }
    // stage X tile [64][256]
    {
        const float* xb = x + (size_t)b*NC*HWSZ + p0;
        for (int i = tid; i < (NC*PTILE)/4; i += 160) {
            int c = i >> 6, j = i & 63;
            float4 v = *reinterpret_cast<const float4*>(xb + (size_t)c*HWSZ + j*4);
            *reinterpret_cast<float4*>(&sX[c*PTILE + j*4]) = v;
        }
    }
    __syncthreads();

    int wid = tid >> 5, lane = tid & 31;
    int obase = wid * 16;

    unsigned long long acc[8][8];   // [opair][pixslot]
#pragma unroll
    for (int i = 0; i < 8; i++) {
        unsigned long long bp = pack2(sB[obase + 2*i], sB[obase + 2*i + 1]);
#pragma unroll
        for (int j = 0; j < 8; j++) acc[i][j] = bp;
    }

#pragma unroll 2
    for (int c = 0; c < NC; c++) {
        const float* xr = &sX[c*PTILE + lane];
        unsigned long long xd[8];
#pragma unroll
        for (int j = 0; j < 8; j++) {
            float xv = xr[32*j];
            xd[j] = pack2(xv, xv);
        }
        const unsigned long long* wr =
            reinterpret_cast<const unsigned long long*>(&sW[c*NOUT + obase]);
#pragma unroll
        for (int i = 0; i < 8; i++) {
            unsigned long long wp = wr[i];
#pragma unroll
            for (int j = 0; j < 8; j++) ffma2(acc[i][j], xd[j], wp);
        }
    }

    // epilogue: warps 0-3 -> V rows; warp 4 -> Q (64-71) + K (72-79) softplus
    float* Vb = g_V + (size_t)b*NC*HWSZ + p0;
    float* Qb = g_Q + (size_t)b*QD*HWSZ + p0;
    float* Kb = g_K + (size_t)b*QD*HWSZ + p0;
#pragma unroll
    for (int i = 0; i < 8; i++) {
        int o = obase + 2*i;
#pragma unroll
        for (int j = 0; j < 8; j++) {
            float f0, f1;
            unpack2(acc[i][j], f0, f1);
            int px = lane + 32*j;
            if (o < 64) {
                Vb[(size_t)o*HWSZ + px]     = f0;
                Vb[(size_t)(o+1)*HWSZ + px] = f1;
            } else if (o < 72) {
                Qb[(size_t)(o-64)*HWSZ + px] = softplusf(f0);
                Qb[(size_t)(o-63)*HWSZ + px] = softplusf(f1);
            } else {
                Kb[(size_t)(o-72)*HWSZ + px] = softplusf(f0);
                Kb[(size_t)(o-71)*HWSZ + px] = softplusf(f1);
            }
        }
    }
}

// ---------------------------------------------------------------
// Kernel B: M_W[b,h,c,q] = sum_w V[b,c,h,w] * K[b,q,h,w]
// ---------------------------------------------------------------
__global__ void __launch_bounds__(256) kmw()
{
    __shared__ float sV[NC*129];
    __shared__ float sK[QD*129];
    int tid = threadIdx.x;
    int b = blockIdx.x / NH, h = blockIdx.x % NH;
    const float* Vrow = g_V + (size_t)b*NC*HWSZ + h*NW;
    const float* Krow = g_K + (size_t)b*QD*HWSZ + h*NW;

#pragma unroll
    for (int i = 0; i < 8; i++) {
        int idx4 = tid + i*256;
        int c = idx4 >> 5, r = idx4 & 31;
        float4 v = *reinterpret_cast<const float4*>(Vrow + (size_t)c*HWSZ + r*4);
        sV[c*129 + r*4 + 0] = v.x; sV[c*129 + r*4 + 1] = v.y;
        sV[c*129 + r*4 + 2] = v.z; sV[c*129 + r*4 + 3] = v.w;
    }
    {
        int q = tid >> 5, r = tid & 31;
        float4 v = *reinterpret_cast<const float4*>(Krow + (size_t)q*HWSZ + r*4);
        sK[q*129 + r*4 + 0] = v.x; sK[q*129 + r*4 + 1] = v.y;
        sK[q*129 + r*4 + 2] = v.z; sK[q*129 + r*4 + 3] = v.w;
    }
    __syncthreads();

    int c = tid >> 2;
    int q0 = (tid & 3) * 2;
    float a0 = 0.f, a1 = 0.f;
#pragma unroll 4
    for (int w = 0; w < NW; w++) {
        float v = sV[c*129 + w];
        a0 = fmaf(v, sK[q0*129 + w],     a0);
        a1 = fmaf(v, sK[(q0+1)*129 + w], a1);
    }
    float2* out = reinterpret_cast<float2*>(g_MW + ((size_t)b*NH + h)*NC*QD);
    out[tid] = make_float2(a0, a1);
}

// ---------------------------------------------------------------
// Kernel C: M_H[b,(c*8+q),w] = sum_h V[b,c,h,w] * K[b,q,h,w]
// ---------------------------------------------------------------
__global__ void __launch_bounds__(1024) kmh()
{
    __shared__ float sV[NC*4*32];
    __shared__ float sK[QD*4*32];
    int tid = threadIdx.x;
    int b = blockIdx.x >> 2;
    int w0 = (blockIdx.x & 3) * 32;
    int w = tid & 31, ch = tid >> 5;

    float acc[16];
#pragma unroll
    for (int i = 0; i < 16; i++) acc[i] = 0.f;

    const float* Vb = g_V + (size_t)b*NC*HWSZ + w0;
    const float* Kb = g_K + (size_t)b*QD*HWSZ + w0;

    for (int h0 = 0; h0 < NH; h0 += 4) {
        __syncthreads();
#pragma unroll
        for (int i = 0; i < 2; i++) {
            int idx4 = tid + i*1024;
            int c = idx4 >> 5, rem = idx4 & 31;
            int hh = rem >> 3, j = rem & 7;
            float4 v = *reinterpret_cast<const float4*>(
                Vb + (size_t)c*HWSZ + (h0 + hh)*NW + j*4);
            *reinterpret_cast<float4*>(&sV[(c*4 + hh)*32 + j*4]) = v;
        }
        if (tid < 256) {
            int q = tid >> 5, rem = tid & 31;
            int hh = rem >> 3, j = rem & 7;
            float4 v = *reinterpret_cast<const float4*>(
                Kb + (size_t)q*HWSZ + (h0 + hh)*NW + j*4);
            *reinterpret_cast<float4*>(&sK[(q*4 + hh)*32 + j*4]) = v;
        }
        __syncthreads();
#pragma unroll
        for (int hh = 0; hh < 4; hh++) {
            float v0 = sV[(ch*4 + hh)*32 + w];
            float v1 = sV[((ch + 32)*4 + hh)*32 + w];
#pragma unroll
            for (int q = 0; q < QD; q++) {
                float kk = sK[(q*4 + hh)*32 + w];
                acc[q]     = fmaf(v0, kk, acc[q]);
                acc[8 + q] = fmaf(v1, kk, acc[8 + q]);
            }
        }
    }
    float* out = g_MH + (size_t)b*NC*QD*NW + w0 + w;
#pragma unroll
    for (int q = 0; q < QD; q++) {
        out[(size_t)(ch*QD + q)*NW]        = acc[q];
        out[(size_t)((ch + 32)*QD + q)*NW] = acc[8 + q];
    }
}

// ---------------------------------------------------------------
// Kernel D: out = gamma*( sum_q Q*(MH+MW) + NEG*V ) + x
// Block = (b, c-half of 32, 8h x 32w). 40KB static smem -> 5 CTAs/SM.
// ---------------------------------------------------------------
__global__ void __launch_bounds__(256, 5) kout(
    const float* __restrict__ x,
    const float* __restrict__ gamma,
    float* __restrict__ out)
{
    __shared__ __align__(16) float sMH[32*QD*32];
    __shared__ __align__(16) float sMW[8*32*QD];
    int tid = threadIdx.x;
    int w0 = blockIdx.x * 32, h0 = blockIdx.y * 8;
    int b  = blockIdx.z >> 1;
    int c0 = (blockIdx.z & 1) * 32;
    int lane = tid & 31, hl = tid >> 5;

#pragma unroll
    for (int i = 0; i < 8; i++) {
        int idx4 = tid + i*256;
        int cql = idx4 >> 3, j = idx4 & 7;
        float4 v = *reinterpret_cast<const float4*>(
            g_MH + ((size_t)b*NC*QD + c0*QD + cql)*NW + w0 + j*4);
        *reinterpret_cast<float4*>(&sMH[cql*32 + j*4]) = v;
    }
#pragma unroll
    for (int i = 0; i < 2; i++) {
        int idx4 = tid + i*256;
        int hh = idx4 >> 6, j = idx4 & 63;
        float4 v = *reinterpret_cast<const float4*>(
            g_MW + ((size_t)(b*NH + h0 + hh)*NC + c0)*QD + j*4);
        *reinterpret_cast<float4*>(&sMW[hh*(32*QD) + j*4]) = v;
    }

    int h = h0 + hl, w = w0 + lane;
    float Qr[QD];
#pragma unroll
    for (int q = 0; q < QD; q++)
        Qr[q] = g_Q[((size_t)b*QD + q)*HWSZ + h*NW + w];
    float gm = gamma[0];
    __syncthreads();

    const float* Vp = g_V + ((size_t)b*NC + c0)*HWSZ + h*NW + w;
    const float* Xp = x   + ((size_t)b*NC + c0)*HWSZ + h*NW + w;
    float*       Op = out + ((size_t)b*NC + c0)*HWSZ + h*NW + w;

#pragma unroll
    for (int cc = 0; cc < 32; cc += 4) {
        float v[4], xr[4];
#pragma unroll
        for (int u = 0; u < 4; u++) {
            v[u]  = Vp[(size_t)(cc+u)*HWSZ];
            xr[u] = Xp[(size_t)(cc+u)*HWSZ];
        }
#pragma unroll
        for (int u = 0; u < 4; u++) {
            int c = cc + u;
            const float* mh = &sMH[c*QD*32 + lane];
            const float4* mwp = reinterpret_cast<const float4*>(&sMW[hl*(32*QD) + c*QD]);
            float4 a = mwp[0], bb = mwp[1];
            float acc;
            acc  = (mh[0]   + a.x)  * Qr[0];
            acc += (mh[32]  + a.y)  * Qr[1];
            acc += (mh[64]  + a.z)  * Qr[2];
            acc += (mh[96]  + a.w)  * Qr[3];
            acc += (mh[128] + bb.x) * Qr[4];
            acc += (mh[160] + bb.y) * Qr[5];
            acc += (mh[192] + bb.z) * Qr[6];
            acc += (mh[224] + bb.w) * Qr[7];
            Op[(size_t)c*HWSZ] = fmaf(gm, fmaf(NEGV, v[u], acc), xr[u]);
        }
    }
}

// ---------------------------------------------------------------
extern "C" void kernel_launch(void* const* d_in, const int* in_sizes, int n_in,
                              void* d_out, int out_size)
{
    const float* x     = (const float*)d_in[0];
    const float* wq    = (const float*)d_in[1];
    const float* bq    = (const float*)d_in[2];
    const float* wk    = (const float*)d_in[3];
    const float* bk    = (const float*)d_in[4];
    const float* wv    = (const float*)d_in[5];
    const float* bv    = (const float*)d_in[6];
    const float* gamma = (const float*)d_in[7];
    float* out = (float*)d_out;

    const int smproj = (NC*PTILE + NC*NOUT + NOUT) * sizeof(float);
    cudaFuncSetAttribute(kproj, cudaFuncAttributeMaxDynamicSharedMemorySize, smproj);

    kproj<<<NB*(HWSZ/PTILE), 160, smproj>>>(x, wq, bq, wk, bk, wv, bv);
    kmw<<<NB*NH, 256>>>();
    kmh<<<NB*4, 1024>>>();
    kout<<<dim3(NW/32, NH/8, NB*2), 256>>>(x, gamma, out);
}

// round 5
// speedup vs baseline: 1.4163x; 1.3688x over previous
#include <cuda_runtime.h>
#include <math.h>

#define NB 32
#define NC 64
#define NH 128
#define NW 128
#define QD 8
#define HWSZ (NH*NW)
#define NEGV (-1e4f)
#define NOUT 80          // 64 V + 8 Q + 8 K
#define PTILE 256        // pixels per kproj block

// ---- device scratch ----
__device__ float g_Q[(size_t)NB*QD*HWSZ];     // [b][q][h][w]
__device__ float g_K[(size_t)NB*QD*HWSZ];     // [b][q][h][w]
__device__ float g_V[(size_t)NB*NC*HWSZ];     // [b][c][h][w]
__device__ float g_MH[(size_t)NB*NC*QD*NW];   // [b][c*8+q][w]
__device__ float g_MW[(size_t)NB*NH*NC*QD];   // [b][h][c*8+q]

__device__ __forceinline__ float softplusf(float v) {
    return fmaxf(v, 0.f) + log1pf(expf(-fabsf(v)));
}

// ---------------------------------------------------------------
// Kernel A: 1x1 projections, register-tiled SCALAR GEMM.
// 320 threads = 10 warps; warp owns 8 output rows (warps 8,9 = Q,K).
// Thread tile: 8 outputs x 8 pixels = 64 FFMA per c-step,
// fed by only 4 LDS.128 (2 broadcast weight quads + 2 x quads).
// ---------------------------------------------------------------
__global__ void __launch_bounds__(320) kproj(
    const float* __restrict__ x,
    const float* __restrict__ wq, const float* __restrict__ bq,
    const float* __restrict__ wk, const float* __restrict__ bk,
    const float* __restrict__ wv, const float* __restrict__ bv)
{
    extern __shared__ float sm[];
    float* sX = sm;                       // [c][256]   16384 floats
    float* sW = sm + NC*PTILE;            // [c][80]     5120 floats
    float* sB = sW + NC*NOUT;             // [80]

    int tid = threadIdx.x;
    int b  = blockIdx.x >> 6;
    int p0 = (blockIdx.x & 63) * PTILE;

    // stage weights transposed, LDG-coalesced: sW[c*80+o] = W[o][c]
    for (int i = tid; i < NC*NC; i += 320) {
        int o = i >> 6, c = i & 63;
        sW[c*NOUT + o] = wv[i];
    }
    for (int i = tid; i < QD*NC; i += 320) {
        int o = i >> 6, c = i & 63;
        sW[c*NOUT + 64 + o] = wq[i];
        sW[c*NOUT + 72 + o] = wk[i];
    }
    if (tid < NOUT)
        sB[tid] = (tid < 64) ? bv[tid] : (tid < 72 ? bq[tid-64] : bk[tid-72]);

    {
        const float* xb = x + (size_t)b*NC*HWSZ + p0;
        for (int i = tid; i < (NC*PTILE)/4; i += 320) {
            int c = i >> 6, j = i & 63;
            float4 v = *reinterpret_cast<const float4*>(xb + (size_t)c*HWSZ + j*4);
            *reinterpret_cast<float4*>(&sX[c*PTILE + j*4]) = v;
        }
    }
    __syncthreads();

    int wid = tid >> 5, lane = tid & 31;
    int obase = wid * 8;

    float acc[8][8];
#pragma unroll
    for (int i = 0; i < 8; i++) {
        float bb = sB[obase + i];
#pragma unroll
        for (int j = 0; j < 8; j++) acc[i][j] = bb;
    }

    const float4* sX4 = reinterpret_cast<const float4*>(sX);  // row stride 64
    const float4* sW4 = reinterpret_cast<const float4*>(sW);  // row stride 20

#pragma unroll 2
    for (int c = 0; c < NC; c++) {
        float4 xa = sX4[c*64 + lane];
        float4 xc = sX4[c*64 + 32 + lane];
        float4 wA = sW4[c*20 + wid*2];
        float4 wB = sW4[c*20 + wid*2 + 1];
        float wv8[8] = {wA.x, wA.y, wA.z, wA.w, wB.x, wB.y, wB.z, wB.w};
        float xv8[8] = {xa.x, xa.y, xa.z, xa.w, xc.x, xc.y, xc.z, xc.w};
#pragma unroll
        for (int i = 0; i < 8; i++)
#pragma unroll
            for (int j = 0; j < 8; j++)
                acc[i][j] = fmaf(wv8[i], xv8[j], acc[i][j]);
    }

    // epilogue: pixels = p0 + 4*lane..+3 and p0 + 128 + 4*lane..+3
    if (obase < 64) {
        float* Vb = g_V + (size_t)b*NC*HWSZ + p0;
#pragma unroll
        for (int i = 0; i < 8; i++) {
            int o = obase + i;
            *reinterpret_cast<float4*>(Vb + (size_t)o*HWSZ + 4*lane) =
                make_float4(acc[i][0], acc[i][1], acc[i][2], acc[i][3]);
            *reinterpret_cast<float4*>(Vb + (size_t)o*HWSZ + 128 + 4*lane) =
                make_float4(acc[i][4], acc[i][5], acc[i][6], acc[i][7]);
        }
    } else {
        float* Pb = (obase == 64 ? g_Q : g_K) + (size_t)b*QD*HWSZ + p0;
#pragma unroll
        for (int i = 0; i < 8; i++) {
#pragma unroll
            for (int j = 0; j < 8; j++) acc[i][j] = softplusf(acc[i][j]);
            *reinterpret_cast<float4*>(Pb + (size_t)i*HWSZ + 4*lane) =
                make_float4(acc[i][0], acc[i][1], acc[i][2], acc[i][3]);
            *reinterpret_cast<float4*>(Pb + (size_t)i*HWSZ + 128 + 4*lane) =
                make_float4(acc[i][4], acc[i][5], acc[i][6], acc[i][7]);
        }
    }
}

// ---------------------------------------------------------------
// Kernel B: M_W[b,h,c,q] = sum_w V[b,c,h,w] * K[b,q,h,w]
// ---------------------------------------------------------------
__global__ void __launch_bounds__(256) kmw()
{
    __shared__ float sV[NC*129];
    __shared__ float sK[QD*129];
    int tid = threadIdx.x;
    int b = blockIdx.x / NH, h = blockIdx.x % NH;
    const float* Vrow = g_V + (size_t)b*NC*HWSZ + h*NW;
    const float* Krow = g_K + (size_t)b*QD*HWSZ + h*NW;

#pragma unroll
    for (int i = 0; i < 8; i++) {
        int idx4 = tid + i*256;
        int c = idx4 >> 5, r = idx4 & 31;
        float4 v = *reinterpret_cast<const float4*>(Vrow + (size_t)c*HWSZ + r*4);
        sV[c*129 + r*4 + 0] = v.x; sV[c*129 + r*4 + 1] = v.y;
        sV[c*129 + r*4 + 2] = v.z; sV[c*129 + r*4 + 3] = v.w;
    }
    {
        int q = tid >> 5, r = tid & 31;
        float4 v = *reinterpret_cast<const float4*>(Krow + (size_t)q*HWSZ + r*4);
        sK[q*129 + r*4 + 0] = v.x; sK[q*129 + r*4 + 1] = v.y;
        sK[q*129 + r*4 + 2] = v.z; sK[q*129 + r*4 + 3] = v.w;
    }
    __syncthreads();

    int c = tid >> 2;
    int q0 = (tid & 3) * 2;
    float a0 = 0.f, a1 = 0.f;
#pragma unroll 4
    for (int w = 0; w < NW; w++) {
        float v = sV[c*129 + w];
        a0 = fmaf(v, sK[q0*129 + w],     a0);
        a1 = fmaf(v, sK[(q0+1)*129 + w], a1);
    }
    float2* out = reinterpret_cast<float2*>(g_MW + ((size_t)b*NH + h)*NC*QD);
    out[tid] = make_float2(a0, a1);
}

// ---------------------------------------------------------------
// Kernel C: M_H[b,(c*8+q),w] = sum_h V[b,c,h,w] * K[b,q,h,w]
// ---------------------------------------------------------------
__global__ void __launch_bounds__(1024) kmh()
{
    __shared__ float sV[NC*4*32];
    __shared__ float sK[QD*4*32];
    int tid = threadIdx.x;
    int b = blockIdx.x >> 2;
    int w0 = (blockIdx.x & 3) * 32;
    int w = tid & 31, ch = tid >> 5;

    float acc[16];
#pragma unroll
    for (int i = 0; i < 16; i++) acc[i] = 0.f;

    const float* Vb = g_V + (size_t)b*NC*HWSZ + w0;
    const float* Kb = g_K + (size_t)b*QD*HWSZ + w0;

    for (int h0 = 0; h0 < NH; h0 += 4) {
        __syncthreads();
#pragma unroll
        for (int i = 0; i < 2; i++) {
            int idx4 = tid + i*1024;
            int c = idx4 >> 5, rem = idx4 & 31;
            int hh = rem >> 3, j = rem & 7;
            float4 v = *reinterpret_cast<const float4*>(
                Vb + (size_t)c*HWSZ + (h0 + hh)*NW + j*4);
            *reinterpret_cast<float4*>(&sV[(c*4 + hh)*32 + j*4]) = v;
        }
        if (tid < 256) {
            int q = tid >> 5, rem = tid & 31;
            int hh = rem >> 3, j = rem & 7;
            float4 v = *reinterpret_cast<const float4*>(
                Kb + (size_t)q*HWSZ + (h0 + hh)*NW + j*4);
            *reinterpret_cast<float4*>(&sK[(q*4 + hh)*32 + j*4]) = v;
        }
        __syncthreads();
#pragma unroll
        for (int hh = 0; hh < 4; hh++) {
            float v0 = sV[(ch*4 + hh)*32 + w];
            float v1 = sV[((ch + 32)*4 + hh)*32 + w];
#pragma unroll
            for (int q = 0; q < QD; q++) {
                float kk = sK[(q*4 + hh)*32 + w];
                acc[q]     = fmaf(v0, kk, acc[q]);
                acc[8 + q] = fmaf(v1, kk, acc[8 + q]);
            }
        }
    }
    float* out = g_MH + (size_t)b*NC*QD*NW + w0 + w;
#pragma unroll
    for (int q = 0; q < QD; q++) {
        out[(size_t)(ch*QD + q)*NW]        = acc[q];
        out[(size_t)((ch + 32)*QD + q)*NW] = acc[8 + q];
    }
}

// ---------------------------------------------------------------
// Kernel D: out = gamma*( sum_q Q*(MH+MW) + NEG*V ) + x
// ---------------------------------------------------------------
__global__ void __launch_bounds__(256, 5) kout(
    const float* __restrict__ x,
    const float* __restrict__ gamma,
    float* __restrict__ out)
{
    __shared__ __align__(16) float sMH[32*QD*32];
    __shared__ __align__(16) float sMW[8*32*QD];
    int tid = threadIdx.x;
    int w0 = blockIdx.x * 32, h0 = blockIdx.y * 8;
    int b  = blockIdx.z >> 1;
    int c0 = (blockIdx.z & 1) * 32;
    int lane = tid & 31, hl = tid >> 5;

#pragma unroll
    for (int i = 0; i < 8; i++) {
        int idx4 = tid + i*256;
        int cql = idx4 >> 3, j = idx4 & 7;
        float4 v = *reinterpret_cast<const float4*>(
            g_MH + ((size_t)b*NC*QD + c0*QD + cql)*NW + w0 + j*4);
        *reinterpret_cast<float4*>(&sMH[cql*32 + j*4]) = v;
    }
#pragma unroll
    for (int i = 0; i < 2; i++) {
        int idx4 = tid + i*256;
        int hh = idx4 >> 6, j = idx4 & 63;
        float4 v = *reinterpret_cast<const float4*>(
            g_MW + ((size_t)(b*NH + h0 + hh)*NC + c0)*QD + j*4);
        *reinterpret_cast<float4*>(&sMW[hh*(32*QD) + j*4]) = v;
    }

    int h = h0 + hl, w = w0 + lane;
    float Qr[QD];
#pragma unroll
    for (int q = 0; q < QD; q++)
        Qr[q] = g_Q[((size_t)b*QD + q)*HWSZ + h*NW + w];
    float gm = gamma[0];
    __syncthreads();

    const float* Vp = g_V + ((size_t)b*NC + c0)*HWSZ + h*NW + w;
    const float* Xp = x   + ((size_t)b*NC + c0)*HWSZ + h*NW + w;
    float*       Op = out + ((size_t)b*NC + c0)*HWSZ + h*NW + w;

#pragma unroll
    for (int cc = 0; cc < 32; cc += 4) {
        float v[4], xr[4];
#pragma unroll
        for (int u = 0; u < 4; u++) {
            v[u]  = Vp[(size_t)(cc+u)*HWSZ];
            xr[u] = Xp[(size_t)(cc+u)*HWSZ];
        }
#pragma unroll
        for (int u = 0; u < 4; u++) {
            int c = cc + u;
            const float* mh = &sMH[c*QD*32 + lane];
            const float4* mwp = reinterpret_cast<const float4*>(&sMW[hl*(32*QD) + c*QD]);
            float4 a = mwp[0], bb = mwp[1];
            float acc;
            acc  = (mh[0]   + a.x)  * Qr[0];
            acc += (mh[32]  + a.y)  * Qr[1];
            acc += (mh[64]  + a.z)  * Qr[2];
            acc += (mh[96]  + a.w)  * Qr[3];
            acc += (mh[128] + bb.x) * Qr[4];
            acc += (mh[160] + bb.y) * Qr[5];
            acc += (mh[192] + bb.z) * Qr[6];
            acc += (mh[224] + bb.w) * Qr[7];
            Op[(size_t)c*HWSZ] = fmaf(gm, fmaf(NEGV, v[u], acc), xr[u]);
        }
    }
}

// ---------------------------------------------------------------
extern "C" void kernel_launch(void* const* d_in, const int* in_sizes, int n_in,
                              void* d_out, int out_size)
{
    const float* x     = (const float*)d_in[0];
    const float* wq    = (const float*)d_in[1];
    const float* bq    = (const float*)d_in[2];
    const float* wk    = (const float*)d_in[3];
    const float* bk    = (const float*)d_in[4];
    const float* wv    = (const float*)d_in[5];
    const float* bv    = (const float*)d_in[6];
    const float* gamma = (const float*)d_in[7];
    float* out = (float*)d_out;

    const int smproj = (NC*PTILE + NC*NOUT + NOUT) * sizeof(float);
    cudaFuncSetAttribute(kproj, cudaFuncAttributeMaxDynamicSharedMemorySize, smproj);

    kproj<<<NB*(HWSZ/PTILE), 320, smproj>>>(x, wq, bq, wk, bk, wv, bv);
    kmw<<<NB*NH, 256>>>();
    kmh<<<NB*4, 1024>>>();
    kout<<<dim3(NW/32, NH/8, NB*2), 256>>>(x, gamma, out);
}

// round 6
// speedup vs baseline: 1.5168x; 1.0710x over previous
#include <cuda_runtime.h>
#include <math.h>

#define NB 32
#define NC 64
#define NH 128
#define NW 128
#define QD 8
#define HWSZ (NH*NW)
#define NEGV (-1e4f)
#define NOUT 80          // 64 V + 8 Q + 8 K
#define PTILE 256        // pixels per kproj block

// ---- device scratch ----
__device__ float g_Q[(size_t)NB*QD*HWSZ];     // [b][q][h][w]
__device__ float g_K[(size_t)NB*QD*HWSZ];     // [b][q][h][w]
__device__ float g_V[(size_t)NB*NC*HWSZ];     // [b][c][h][w]
__device__ float g_MH[(size_t)NB*NC*QD*NW];   // [b][c*8+q][w]
__device__ float g_MW[(size_t)NB*NH*NC*QD];   // [b][h][c*8+q]

__device__ __forceinline__ float softplusf(float v) {
    return fmaxf(v, 0.f) + log1pf(expf(-fabsf(v)));
}

// ---------------------------------------------------------------
// Kernel A: 1x1 projections, register-tiled SCALAR GEMM.
// 320 threads = 10 warps; warp owns 8 output rows (warps 8,9 = Q,K).
// Thread tile: 8 outputs x 8 pixels = 64 FFMA per c-step,
// fed by only 4 LDS.128 (2 broadcast weight quads + 2 x quads).
// ---------------------------------------------------------------
__global__ void __launch_bounds__(320) kproj(
    const float* __restrict__ x,
    const float* __restrict__ wq, const float* __restrict__ bq,
    const float* __restrict__ wk, const float* __restrict__ bk,
    const float* __restrict__ wv, const float* __restrict__ bv)
{
    extern __shared__ float sm[];
    float* sX = sm;                       // [c][256]   16384 floats
    float* sW = sm + NC*PTILE;            // [c][80]     5120 floats
    float* sB = sW + NC*NOUT;             // [80]

    int tid = threadIdx.x;
    int b  = blockIdx.x >> 6;
    int p0 = (blockIdx.x & 63) * PTILE;

    // stage weights transposed, LDG-coalesced: sW[c*80+o] = W[o][c]
    for (int i = tid; i < NC*NC; i += 320) {
        int o = i >> 6, c = i & 63;
        sW[c*NOUT + o] = wv[i];
    }
    for (int i = tid; i < QD*NC; i += 320) {
        int o = i >> 6, c = i & 63;
        sW[c*NOUT + 64 + o] = wq[i];
        sW[c*NOUT + 72 + o] = wk[i];
    }
    if (tid < NOUT)
        sB[tid] = (tid < 64) ? bv[tid] : (tid < 72 ? bq[tid-64] : bk[tid-72]);

    {
        const float* xb = x + (size_t)b*NC*HWSZ + p0;
        for (int i = tid; i < (NC*PTILE)/4; i += 320) {
            int c = i >> 6, j = i & 63;
            float4 v = *reinterpret_cast<const float4*>(xb + (size_t)c*HWSZ + j*4);
            *reinterpret_cast<float4*>(&sX[c*PTILE + j*4]) = v;
        }
    }
    __syncthreads();

    int wid = tid >> 5, lane = tid & 31;
    int obase = wid * 8;

    float acc[8][8];
#pragma unroll
    for (int i = 0; i < 8; i++) {
        float bb = sB[obase + i];
#pragma unroll
        for (int j = 0; j < 8; j++) acc[i][j] = bb;
    }

    const float4* sX4 = reinterpret_cast<const float4*>(sX);  // row stride 64
    const float4* sW4 = reinterpret_cast<const float4*>(sW);  // row stride 20

#pragma unroll 2
    for (int c = 0; c < NC; c++) {
        float4 xa = sX4[c*64 + lane];
        float4 xc = sX4[c*64 + 32 + lane];
        float4 wA = sW4[c*20 + wid*2];
        float4 wB = sW4[c*20 + wid*2 + 1];
        float wv8[8] = {wA.x, wA.y, wA.z, wA.w, wB.x, wB.y, wB.z, wB.w};
        float xv8[8] = {xa.x, xa.y, xa.z, xa.w, xc.x, xc.y, xc.z, xc.w};
#pragma unroll
        for (int i = 0; i < 8; i++)
#pragma unroll
            for (int j = 0; j < 8; j++)
                acc[i][j] = fmaf(wv8[i], xv8[j], acc[i][j]);
    }

    // epilogue: pixels = p0 + 4*lane..+3 and p0 + 128 + 4*lane..+3
    if (obase < 64) {
        float* Vb = g_V + (size_t)b*NC*HWSZ + p0;
#pragma unroll
        for (int i = 0; i < 8; i++) {
            int o = obase + i;
            *reinterpret_cast<float4*>(Vb + (size_t)o*HWSZ + 4*lane) =
                make_float4(acc[i][0], acc[i][1], acc[i][2], acc[i][3]);
            *reinterpret_cast<float4*>(Vb + (size_t)o*HWSZ + 128 + 4*lane) =
                make_float4(acc[i][4], acc[i][5], acc[i][6], acc[i][7]);
        }
    } else {
        float* Pb = (obase == 64 ? g_Q : g_K) + (size_t)b*QD*HWSZ + p0;
#pragma unroll
        for (int i = 0; i < 8; i++) {
#pragma unroll
            for (int j = 0; j < 8; j++) acc[i][j] = softplusf(acc[i][j]);
            *reinterpret_cast<float4*>(Pb + (size_t)i*HWSZ + 4*lane) =
                make_float4(acc[i][0], acc[i][1], acc[i][2], acc[i][3]);
            *reinterpret_cast<float4*>(Pb + (size_t)i*HWSZ + 128 + 4*lane) =
                make_float4(acc[i][4], acc[i][5], acc[i][6], acc[i][7]);
        }
    }
}

// ---------------------------------------------------------------
// Kernel B: M_W[b,h,c,q] = sum_w V[b,c,h,w] * K[b,q,h,w]
// float4-vectorized w loop; smem stride 132 (16B-aligned, bank-spread).
// per thread: 96 LDS.128 + 256 FFMA (was 384 scalar LDS).
// ---------------------------------------------------------------
__global__ void __launch_bounds__(256) kmw()
{
    __shared__ __align__(16) float sV[NC*132];
    __shared__ __align__(16) float sK[QD*132];
    int tid = threadIdx.x;
    int b = blockIdx.x / NH, h = blockIdx.x % NH;
    const float* Vrow = g_V + (size_t)b*NC*HWSZ + h*NW;
    const float* Krow = g_K + (size_t)b*QD*HWSZ + h*NW;

#pragma unroll
    for (int i = 0; i < 8; i++) {
        int idx4 = tid + i*256;
        int c = idx4 >> 5, r = idx4 & 31;
        float4 v = *reinterpret_cast<const float4*>(Vrow + (size_t)c*HWSZ + r*4);
        *reinterpret_cast<float4*>(&sV[c*132 + r*4]) = v;
    }
    {
        int q = tid >> 5, r = tid & 31;
        float4 v = *reinterpret_cast<const float4*>(Krow + (size_t)q*HWSZ + r*4);
        *reinterpret_cast<float4*>(&sK[q*132 + r*4]) = v;
    }
    __syncthreads();

    int c = tid >> 2;
    int q0 = (tid & 3) * 2;
    float a0 = 0.f, a1 = 0.f;
#pragma unroll 8
    for (int w4 = 0; w4 < NW/4; w4++) {
        float4 v  = *reinterpret_cast<const float4*>(&sV[c*132 + w4*4]);
        float4 k0 = *reinterpret_cast<const float4*>(&sK[q0*132 + w4*4]);
        float4 k1 = *reinterpret_cast<const float4*>(&sK[(q0+1)*132 + w4*4]);
        a0 = fmaf(v.x, k0.x, a0); a0 = fmaf(v.y, k0.y, a0);
        a0 = fmaf(v.z, k0.z, a0); a0 = fmaf(v.w, k0.w, a0);
        a1 = fmaf(v.x, k1.x, a1); a1 = fmaf(v.y, k1.y, a1);
        a1 = fmaf(v.z, k1.z, a1); a1 = fmaf(v.w, k1.w, a1);
    }
    float2* out = reinterpret_cast<float2*>(g_MW + ((size_t)b*NH + h)*NC*QD);
    out[tid] = make_float2(a0, a1);
}

// ---------------------------------------------------------------
// Kernel C: M_H[b,(c*8+q),w] = sum_h V[b,c,h,w] * K[b,q,h,w]
// ---------------------------------------------------------------
__global__ void __launch_bounds__(1024) kmh()
{
    __shared__ float sV[NC*4*32];
    __shared__ float sK[QD*4*32];
    int tid = threadIdx.x;
    int b = blockIdx.x >> 2;
    int w0 = (blockIdx.x & 3) * 32;
    int w = tid & 31, ch = tid >> 5;

    float acc[16];
#pragma unroll
    for (int i = 0; i < 16; i++) acc[i] = 0.f;

    const float* Vb = g_V + (size_t)b*NC*HWSZ + w0;
    const float* Kb = g_K + (size_t)b*QD*HWSZ + w0;

    for (int h0 = 0; h0 < NH; h0 += 4) {
        __syncthreads();
#pragma unroll
        for (int i = 0; i < 2; i++) {
            int idx4 = tid + i*1024;
            int c = idx4 >> 5, rem = idx4 & 31;
            int hh = rem >> 3, j = rem & 7;
            float4 v = *reinterpret_cast<const float4*>(
                Vb + (size_t)c*HWSZ + (h0 + hh)*NW + j*4);
            *reinterpret_cast<float4*>(&sV[(c*4 + hh)*32 + j*4]) = v;
        }
        if (tid < 256) {
            int q = tid >> 5, rem = tid & 31;
            int hh = rem >> 3, j = rem & 7;
            float4 v = *reinterpret_cast<const float4*>(
                Kb + (size_t)q*HWSZ + (h0 + hh)*NW + j*4);
            *reinterpret_cast<float4*>(&sK[(q*4 + hh)*32 + j*4]) = v;
        }
        __syncthreads();
#pragma unroll
        for (int hh = 0; hh < 4; hh++) {
            float v0 = sV[(ch*4 + hh)*32 + w];
            float v1 = sV[((ch + 32)*4 + hh)*32 + w];
#pragma unroll
            for (int q = 0; q < QD; q++) {
                float kk = sK[(q*4 + hh)*32 + w];
                acc[q]     = fmaf(v0, kk, acc[q]);
                acc[8 + q] = fmaf(v1, kk, acc[8 + q]);
            }
        }
    }
    float* out = g_MH + (size_t)b*NC*QD*NW + w0 + w;
#pragma unroll
    for (int q = 0; q < QD; q++) {
        out[(size_t)(ch*QD + q)*NW]        = acc[q];
        out[(size_t)((ch + 32)*QD + q)*NW] = acc[8 + q];
    }
}

// ---------------------------------------------------------------
// Kernel D: out = gamma*( sum_q Q*(MH+MW) + NEG*V ) + x
// Block = (b, c-quarter of 16, 8h x 32w). 20KB smem -> 6 CTAs/SM.
// ---------------------------------------------------------------
__global__ void __launch_bounds__(256, 6) kout(
    const float* __restrict__ x,
    const float* __restrict__ gamma,
    float* __restrict__ out)
{
    __shared__ __align__(16) float sMH[16*QD*32];   // [c_loc*8+q][w32] 16KB
    __shared__ __align__(16) float sMW[8*16*QD];    // [hl][c_loc*8+q]   4KB
    int tid = threadIdx.x;
    int w0 = blockIdx.x * 32, h0 = blockIdx.y * 8;
    int b  = blockIdx.z >> 2;
    int c0 = (blockIdx.z & 3) * 16;
    int lane = tid & 31, hl = tid >> 5;

    // sMH: 16c*8q = 128 rows x 32 w = 4096 floats = 1024 float4
#pragma unroll
    for (int i = 0; i < 4; i++) {
        int idx4 = tid + i*256;
        int cql = idx4 >> 3, j = idx4 & 7;
        float4 v = *reinterpret_cast<const float4*>(
            g_MH + ((size_t)b*NC*QD + c0*QD + cql)*NW + w0 + j*4);
        *reinterpret_cast<float4*>(&sMH[cql*32 + j*4]) = v;
    }
    // sMW: 8 h x 128 floats = 1024 floats = 256 float4
    {
        int hh = tid >> 5, j = tid & 31;
        float4 v = *reinterpret_cast<const float4*>(
            g_MW + ((size_t)(b*NH + h0 + hh)*NC + c0)*QD + j*4);
        *reinterpret_cast<float4*>(&sMW[hh*(16*QD) + j*4]) = v;
    }

    int h = h0 + hl, w = w0 + lane;
    float Qr[QD];
#pragma unroll
    for (int q = 0; q < QD; q++)
        Qr[q] = g_Q[((size_t)b*QD + q)*HWSZ + h*NW + w];
    float gm = gamma[0];
    __syncthreads();

    const float* Vp = g_V + ((size_t)b*NC + c0)*HWSZ + h*NW + w;
    const float* Xp = x   + ((size_t)b*NC + c0)*HWSZ + h*NW + w;
    float*       Op = out + ((size_t)b*NC + c0)*HWSZ + h*NW + w;

#pragma unroll
    for (int cc = 0; cc < 16; cc += 4) {
        float v[4], xr[4];
#pragma unroll
        for (int u = 0; u < 4; u++) {
            v[u]  = Vp[(size_t)(cc+u)*HWSZ];
            xr[u] = Xp[(size_t)(cc+u)*HWSZ];
        }
#pragma unroll
        for (int u = 0; u < 4; u++) {
            int c = cc + u;
            const float* mh = &sMH[c*QD*32 + lane];
            const float4* mwp = reinterpret_cast<const float4*>(&sMW[hl*(16*QD) + c*QD]);
            float4 a = mwp[0], bb = mwp[1];
            float acc;
            acc  = (mh[0]   + a.x)  * Qr[0];
            acc += (mh[32]  + a.y)  * Qr[1];
            acc += (mh[64]  + a.z)  * Qr[2];
            acc += (mh[96]  + a.w)  * Qr[3];
            acc += (mh[128] + bb.x) * Qr[4];
            acc += (mh[160] + bb.y) * Qr[5];
            acc += (mh[192] + bb.z) * Qr[6];
            acc += (mh[224] + bb.w) * Qr[7];
            Op[(size_t)c*HWSZ] = fmaf(gm, fmaf(NEGV, v[u], acc), xr[u]);
        }
    }
}

// ---------------------------------------------------------------
extern "C" void kernel_launch(void* const* d_in, const int* in_sizes, int n_in,
                              void* d_out, int out_size)
{
    const float* x     = (const float*)d_in[0];
    const float* wq    = (const float*)d_in[1];
    const float* bq    = (const float*)d_in[2];
    const float* wk    = (const float*)d_in[3];
    const float* bk    = (const float*)d_in[4];
    const float* wv    = (const float*)d_in[5];
    const float* bv    = (const float*)d_in[6];
    const float* gamma = (const float*)d_in[7];
    float* out = (float*)d_out;

    const int smproj = (NC*PTILE + NC*NOUT + NOUT) * sizeof(float);
    cudaFuncSetAttribute(kproj, cudaFuncAttributeMaxDynamicSharedMemorySize, smproj);

    kproj<<<NB*(HWSZ/PTILE), 320, smproj>>>(x, wq, bq, wk, bk, wv, bv);
    kmw<<<NB*NH, 256>>>();
    kmh<<<NB*4, 1024>>>();
    kout<<<dim3(NW/32, NH/8, NB*4), 256>>>(x, gamma, out);
}